// round 7
// baseline (speedup 1.0000x reference)
#include <cuda_runtime.h>
#include <cuda_bf16.h>
#include <cstdint>

#define NNODES 22
#define TB     500
#define BATCH  256
#define MROWS  (BATCH*NNODES)   // 5632
#define HOPP   512              // padded per-hop K stride
#define KBLK   1536             // per split-block K (3 hops x 512)
#define KTOT   4608             // [Xh | Xl | Xh] K
#define NTOT   512              // padded N

#define BM 128
#define BN 128
#define BK2 16
#define KT2 (KTOT/BK2)          // 288
#define STAGES 3
#define THREADS 256

typedef unsigned long long u64;

// ---------------- device scratch ------------------------------------------
__device__ float         g_A [NNODES*NNODES];
__device__ float         g_A2[NNODES*NNODES];
__device__ __nv_bfloat16 g_Xbf[(size_t)MROWS*KTOT];   // 51.9 MB
__device__ __nv_bfloat16 g_Wbf[(size_t)NTOT*KTOT];    // 4.7 MB
__device__ float         g_C  [(size_t)MROWS*NTOT];   // 11.5 MB

// ---------------------------------------------------------------------------
// Kernel 1: A = softmax(adj), A2 = A@A
// ---------------------------------------------------------------------------
__global__ void prep_adj_kernel(const float* __restrict__ adj) {
    __shared__ float sA[NNODES*NNODES];
    int tid = threadIdx.x;
    if (tid < NNODES) {
        float e[NNODES], mx = -1e30f;
        #pragma unroll
        for (int j = 0; j < NNODES; j++) mx = fmaxf(mx, adj[tid*NNODES + j]);
        float s = 0.f;
        #pragma unroll
        for (int j = 0; j < NNODES; j++) { e[j] = expf(adj[tid*NNODES + j] - mx); s += e[j]; }
        float inv = 1.f / s;
        #pragma unroll
        for (int j = 0; j < NNODES; j++) {
            float v = e[j] * inv;
            sA[tid*NNODES + j] = v;
            g_A[tid*NNODES + j] = v;
        }
    }
    __syncthreads();
    if (tid < NNODES*NNODES) {
        int n = tid / NNODES, m = tid - n*NNODES;
        float s = 0.f;
        #pragma unroll
        for (int k = 0; k < NNODES; k++) s = fmaf(sA[n*NNODES + k], sA[k*NNODES + m], s);
        g_A2[tid] = s;
    }
}

// ---------------------------------------------------------------------------
// Kernel 2: g_Xbf = bf16 split of [x | Ax | A2x], K-blocks [hi | lo | hi]
// ---------------------------------------------------------------------------
__global__ __launch_bounds__(512) void build_xbf_kernel(const float* __restrict__ x) {
    __shared__ float sA[NNODES*NNODES], sA2[NNODES*NNODES];
    const int b = blockIdx.x;
    for (int i = threadIdx.x; i < NNODES*NNODES; i += blockDim.x) {
        sA[i] = g_A[i]; sA2[i] = g_A2[i];
    }
    __syncthreads();

    const int t = threadIdx.x;
    __nv_bfloat16* Xb = g_Xbf + (size_t)b * NNODES * KTOT;

    if (t < TB) {
        float xv[NNODES];
        const float* xb = x + (size_t)b * NNODES * TB;
        #pragma unroll
        for (int m = 0; m < NNODES; m++) xv[m] = xb[m*TB + t];
        #pragma unroll
        for (int n = 0; n < NNODES; n++) {
            float h1 = 0.f, h2 = 0.f;
            #pragma unroll
            for (int m = 0; m < NNODES; m++) {
                h1 = fmaf(sA [n*NNODES + m], xv[m], h1);
                h2 = fmaf(sA2[n*NNODES + m], xv[m], h2);
            }
            float v0 = xv[n];
            __nv_bfloat16 hi0 = __float2bfloat16(v0);
            __nv_bfloat16 hi1 = __float2bfloat16(h1);
            __nv_bfloat16 hi2 = __float2bfloat16(h2);
            __nv_bfloat16 lo0 = __float2bfloat16(v0 - __bfloat162float(hi0));
            __nv_bfloat16 lo1 = __float2bfloat16(h1 - __bfloat162float(hi1));
            __nv_bfloat16 lo2 = __float2bfloat16(h2 - __bfloat162float(hi2));
            __nv_bfloat16* R = Xb + (size_t)n * KTOT;
            R[t] = hi0;  R[HOPP + t] = hi1;  R[2*HOPP + t] = hi2;
            R[KBLK + t] = lo0;  R[KBLK + HOPP + t] = lo1;  R[KBLK + 2*HOPP + t] = lo2;
            R[2*KBLK + t] = hi0;  R[2*KBLK + HOPP + t] = hi1;  R[2*KBLK + 2*HOPP + t] = hi2;
        }
    } else {  // t in [500, 512): zero padding columns
        __nv_bfloat16 z = __float2bfloat16(0.f);
        #pragma unroll
        for (int n = 0; n < NNODES; n++) {
            __nv_bfloat16* R = Xb + (size_t)n * KTOT;
            #pragma unroll
            for (int blk = 0; blk < 3; blk++)
                #pragma unroll
                for (int hop = 0; hop < 3; hop++)
                    R[blk*KBLK + hop*HOPP + t] = z;
        }
    }
}

// ---------------------------------------------------------------------------
// Kernel 3: g_Wbf[n][k] (K-major B), blocks [Wh | Wh | Wl]
// ---------------------------------------------------------------------------
__global__ __launch_bounds__(512) void build_wbf_kernel(const float* __restrict__ W) {
    const int n = blockIdx.x;   // 0..511
    for (int k = threadIdx.x; k < KTOT; k += 512) {
        int blk = k / KBLK;
        int kk  = k - blk*KBLK;
        int hop = kk >> 9;
        int tp  = kk & 511;
        float v = 0.f;
        if (tp < TB && n < TB) v = W[((size_t)hop*TB + tp)*TB + n];
        __nv_bfloat16 hv = __float2bfloat16(v);
        __nv_bfloat16 ov = hv;
        if (blk == 2) ov = __float2bfloat16(v - __bfloat162float(hv));
        g_Wbf[(size_t)n*KTOT + k] = ov;
    }
}

// ---------------------------------------------------------------------------
// Kernel 4: mma.sync bf16 GEMM: g_C = Xbf * Wbf^T (both K-major)
//   block 128x128x16, 256 thr (8 warps, warp tile 64x32), 3-stage cp.async,
//   2 CTAs per SM, grid 176 (all resident in one wave).
// ---------------------------------------------------------------------------

// Swizzle for 32B rows packed as 128B atoms of 4 rows; conflict-free for
// ldmatrix 8-row phases (atom keys k / k^1 give disjoint bit0 slot sets)
// and for cp.async 16B stores.
__device__ __forceinline__ uint32_t sw32(int r, int c) {
    int chunk = ((r & 3) << 1) | c;
    return (uint32_t)((r >> 2) * 128 + ((chunk ^ ((r >> 2) & 7)) << 4));
}

__device__ __forceinline__ uint32_t smem_u32(const void* p) {
    uint32_t a;
    asm("{ .reg .u64 t; cvta.to.shared.u64 t, %1; cvt.u32.u64 %0, t; }" : "=r"(a) : "l"(p));
    return a;
}
__device__ __forceinline__ void cp16(uint32_t dst, const void* src) {
    asm volatile("cp.async.cg.shared.global [%0], [%1], 16;" :: "r"(dst), "l"(src));
}
__device__ __forceinline__ void ldm_x4(uint32_t* q, uint32_t addr) {
    asm volatile("ldmatrix.sync.aligned.m8n8.x4.shared.b16 {%0,%1,%2,%3}, [%4];"
                 : "=r"(q[0]), "=r"(q[1]), "=r"(q[2]), "=r"(q[3]) : "r"(addr));
}
__device__ __forceinline__ void mma_bf16(float* c, const uint32_t* a, uint32_t b0, uint32_t b1) {
    asm volatile("mma.sync.aligned.m16n8k16.row.col.f32.bf16.bf16.f32 "
                 "{%0,%1,%2,%3}, {%4,%5,%6,%7}, {%8,%9}, {%0,%1,%2,%3};"
                 : "+f"(c[0]), "+f"(c[1]), "+f"(c[2]), "+f"(c[3])
                 : "r"(a[0]), "r"(a[1]), "r"(a[2]), "r"(a[3]), "r"(b0), "r"(b1));
}

#define A_ST 4096   // 128 rows * 32B
#define B_ST 4096

__global__ void __launch_bounds__(THREADS, 2) gemm_mma_kernel() {
    __shared__ __align__(128) unsigned char smem[STAGES*(A_ST + B_ST)];  // 24 KB

    const int tid  = threadIdx.x;
    const int lane = tid & 31;
    const int wid  = tid >> 5;
    const int wm   = wid & 1;        // 2 warps over M (64 rows each)
    const int wn   = wid >> 1;       // 4 warps over N (32 cols each)
    const int row0 = blockIdx.y * BM;
    const int n0   = blockIdx.x * BN;

    const uint32_t sA0 = smem_u32(smem);
    const uint32_t sB0 = sA0 + STAGES*A_ST;

    const char* gA = reinterpret_cast<const char*>(g_Xbf);
    const char* gB = reinterpret_cast<const char*>(g_Wbf);

    // per-thread load mapping: one 16B chunk of A and one of B per stage
    const int l_r = tid >> 1, l_c = tid & 1;
    const uint32_t aoff = sw32(l_r, l_c);
    const uint32_t boff = sw32(l_r, l_c);
    const char* aptr = gA + ((size_t)(row0 + l_r) * KTOT + l_c*8) * 2;
    const char* bptr = gB + ((size_t)(n0   + l_r) * KTOT + l_c*8) * 2;

    float acc[4][4][4];
    #pragma unroll
    for (int i = 0; i < 4; i++)
        #pragma unroll
        for (int j = 0; j < 4; j++)
            #pragma unroll
            for (int q = 0; q < 4; q++) acc[i][j][q] = 0.f;

    // prologue: stages 0 and 1
    #pragma unroll
    for (int s = 0; s < 2; s++) {
        const size_t kbyte = (size_t)s * BK2 * 2;
        cp16(sA0 + s*A_ST + aoff, aptr + kbyte);
        cp16(sB0 + s*B_ST + boff, bptr + kbyte);
        asm volatile("cp.async.commit_group;" ::: "memory");
    }

    const int lr = lane & 15;          // row within 16-row group
    const int lc = lane >> 4;          // k chunk (0/1)

    int stc = 0;   // stage of kb
    int stl = 2;   // stage to load (kb+2)
    for (int kb = 0; kb < KT2; kb++) {
        asm volatile("cp.async.wait_group 1;" ::: "memory");
        __syncthreads();

        // issue loads for kb+2 (stage stl) — safe: all warps finished kb-1
        const int ns = kb + 2;
        if (ns < KT2) {
            const size_t kbyte = (size_t)ns * BK2 * 2;
            cp16(sA0 + stl*A_ST + aoff, aptr + kbyte);
            cp16(sB0 + stl*B_ST + boff, bptr + kbyte);
        }
        asm volatile("cp.async.commit_group;" ::: "memory");

        // compute stage stc
        const uint32_t sa = sA0 + stc*A_ST;
        const uint32_t sb = sB0 + stc*B_ST;

        uint32_t af[4][4];
        #pragma unroll
        for (int mi = 0; mi < 4; mi++)
            ldm_x4(af[mi], sa + sw32(wm*64 + mi*16 + lr, lc));
        uint32_t bq0[4], bq1[4];
        ldm_x4(bq0, sb + sw32(wn*32 +  0 + lr, lc));
        ldm_x4(bq1, sb + sw32(wn*32 + 16 + lr, lc));

        #pragma unroll
        for (int mi = 0; mi < 4; mi++) {
            mma_bf16(acc[mi][0], af[mi], bq0[0], bq0[2]);
            mma_bf16(acc[mi][1], af[mi], bq0[1], bq0[3]);
            mma_bf16(acc[mi][2], af[mi], bq1[0], bq1[2]);
            mma_bf16(acc[mi][3], af[mi], bq1[1], bq1[3]);
        }

        stc = (stc == STAGES-1) ? 0 : stc + 1;
        stl = (stl == STAGES-1) ? 0 : stl + 1;
    }

    // ---- epilogue: fragments -> g_C ----
    const int crow = lane >> 2;
    const int ccol = (lane & 3) * 2;
    #pragma unroll
    for (int mi = 0; mi < 4; mi++) {
        const int r = row0 + wm*64 + mi*16 + crow;
        #pragma unroll
        for (int ni = 0; ni < 4; ni++) {
            const int cbase = n0 + wn*32 + ni*8 + ccol;
            *reinterpret_cast<float2*>(&g_C[(size_t)r      *NTOT + cbase]) =
                make_float2(acc[mi][ni][0], acc[mi][ni][1]);
            *reinterpret_cast<float2*>(&g_C[(size_t)(r + 8)*NTOT + cbase]) =
                make_float2(acc[mi][ni][2], acc[mi][ni][3]);
        }
    }
}

// ---------------------------------------------------------------------------
// Kernel 5: out[b, e, n, :] = g_C[b*22+n, 0:500] + bias, for all e
// ---------------------------------------------------------------------------
__global__ __launch_bounds__(256) void replicate_kernel(
    const float* __restrict__ bias, float* __restrict__ out, int E)
{
    const int half = threadIdx.x >> 7;            // 0 or 1
    const int t4   = threadIdx.x & 127;           // float4 index in row
    const int m = blockIdx.x * 2 + half;          // 0..5631
    if (t4 >= TB/4) return;
    const int bb = m / NNODES, nn = m - bb*NNODES;
    float4 v  = *reinterpret_cast<const float4*>(&g_C[(size_t)m*NTOT + t4*4]);
    float4 bv = *reinterpret_cast<const float4*>(&bias[t4*4]);
    v.x += bv.x; v.y += bv.y; v.z += bv.z; v.w += bv.w;
    float* p = out + (size_t)bb * E * (NNODES*TB) + (size_t)nn * TB + t4*4;
    #pragma unroll 4
    for (int e = 0; e < E; e++) {
        *reinterpret_cast<float4*>(p) = v;
        p += NNODES*TB;
    }
}

// ---------------------------------------------------------------------------
// Launch. Inputs: x, adj, W, b, emb_size.
// ---------------------------------------------------------------------------
extern "C" void kernel_launch(void* const* d_in, const int* in_sizes, int n_in,
                              void* d_out, int out_size) {
    const float* x    = (const float*)d_in[0];
    const float* adj  = (const float*)d_in[1];
    const float* Wmat = (const float*)d_in[2];
    const float* bias = (const float*)d_in[3];
    float* out = (float*)d_out;
    const int E = out_size / (BATCH * NNODES * TB);

    prep_adj_kernel<<<1, 512>>>(adj);
    build_xbf_kernel<<<BATCH, 512>>>(x);
    build_wbf_kernel<<<NTOT, 512>>>(Wmat);

    dim3 grid(NTOT / BN, MROWS / BM);   // (4, 44) = 176 blocks, 2/SM
    gemm_mma_kernel<<<grid, THREADS>>>();

    replicate_kernel<<<MROWS/2, 256>>>(bias, out, E);
}

// round 8
// speedup vs baseline: 1.0407x; 1.0407x over previous
#include <cuda_runtime.h>
#include <cuda_bf16.h>
#include <cstdint>

#define NNODES 22
#define TB     500
#define BATCH  256
#define MROWS  (BATCH*NNODES)   // 5632
#define HOPP   512              // padded per-hop K stride
#define KBLK   1536             // per split-block K (3 hops x 512)
#define KTOT   4608             // B: [Wh | Wh | Wl]
#define KTOTA  3072             // A: [Xh | Xl]  (block 2 re-reads block 0)
#define NTOT   512              // padded N

#define BM 128
#define BN 128
#define BK 32
#define KT 144                  // K-chunks of 32 (over B's 4608)
#define STAGES 3
#define THREADS 256

typedef unsigned long long u64;

// ---------------- device scratch ------------------------------------------
__device__ float         g_A [NNODES*NNODES];
__device__ float         g_A2[NNODES*NNODES];
__device__ __nv_bfloat16 g_Xbf[(size_t)MROWS*KTOTA];  // 34.6 MB
__device__ __nv_bfloat16 g_Wbf[(size_t)NTOT*KTOT];    // 4.7 MB
__device__ float         g_C  [(size_t)MROWS*NTOT];   // 11.5 MB

// ---------------------------------------------------------------------------
// Kernel 1: A = softmax(adj), A2 = A@A
// ---------------------------------------------------------------------------
__global__ void prep_adj_kernel(const float* __restrict__ adj) {
    __shared__ float sA[NNODES*NNODES];
    int tid = threadIdx.x;
    if (tid < NNODES) {
        float e[NNODES], mx = -1e30f;
        #pragma unroll
        for (int j = 0; j < NNODES; j++) mx = fmaxf(mx, adj[tid*NNODES + j]);
        float s = 0.f;
        #pragma unroll
        for (int j = 0; j < NNODES; j++) { e[j] = expf(adj[tid*NNODES + j] - mx); s += e[j]; }
        float inv = 1.f / s;
        #pragma unroll
        for (int j = 0; j < NNODES; j++) {
            float v = e[j] * inv;
            sA[tid*NNODES + j] = v;
            g_A[tid*NNODES + j] = v;
        }
    }
    __syncthreads();
    if (tid < NNODES*NNODES) {
        int n = tid / NNODES, m = tid - n*NNODES;
        float s = 0.f;
        #pragma unroll
        for (int k = 0; k < NNODES; k++) s = fmaf(sA[n*NNODES + k], sA[k*NNODES + m], s);
        g_A2[tid] = s;
    }
}

// ---------------------------------------------------------------------------
// Kernel 2: g_Xbf = bf16 split of [x | Ax | A2x], K-blocks [hi | lo]
// ---------------------------------------------------------------------------
__global__ __launch_bounds__(512) void build_xbf_kernel(const float* __restrict__ x) {
    __shared__ float sA[NNODES*NNODES], sA2[NNODES*NNODES];
    const int b = blockIdx.x;
    for (int i = threadIdx.x; i < NNODES*NNODES; i += blockDim.x) {
        sA[i] = g_A[i]; sA2[i] = g_A2[i];
    }
    __syncthreads();

    const int t = threadIdx.x;
    __nv_bfloat16* Xb = g_Xbf + (size_t)b * NNODES * KTOTA;

    if (t < TB) {
        float xv[NNODES];
        const float* xb = x + (size_t)b * NNODES * TB;
        #pragma unroll
        for (int m = 0; m < NNODES; m++) xv[m] = xb[m*TB + t];
        #pragma unroll
        for (int n = 0; n < NNODES; n++) {
            float h1 = 0.f, h2 = 0.f;
            #pragma unroll
            for (int m = 0; m < NNODES; m++) {
                h1 = fmaf(sA [n*NNODES + m], xv[m], h1);
                h2 = fmaf(sA2[n*NNODES + m], xv[m], h2);
            }
            float v0 = xv[n];
            __nv_bfloat16 hi0 = __float2bfloat16(v0);
            __nv_bfloat16 hi1 = __float2bfloat16(h1);
            __nv_bfloat16 hi2 = __float2bfloat16(h2);
            __nv_bfloat16 lo0 = __float2bfloat16(v0 - __bfloat162float(hi0));
            __nv_bfloat16 lo1 = __float2bfloat16(h1 - __bfloat162float(hi1));
            __nv_bfloat16 lo2 = __float2bfloat16(h2 - __bfloat162float(hi2));
            __nv_bfloat16* R = Xb + (size_t)n * KTOTA;
            R[t] = hi0;  R[HOPP + t] = hi1;  R[2*HOPP + t] = hi2;
            R[KBLK + t] = lo0;  R[KBLK + HOPP + t] = lo1;  R[KBLK + 2*HOPP + t] = lo2;
        }
    } else {  // t in [500, 512): zero padding columns
        __nv_bfloat16 z = __float2bfloat16(0.f);
        #pragma unroll
        for (int n = 0; n < NNODES; n++) {
            __nv_bfloat16* R = Xb + (size_t)n * KTOTA;
            #pragma unroll
            for (int blk = 0; blk < 2; blk++)
                #pragma unroll
                for (int hop = 0; hop < 3; hop++)
                    R[blk*KBLK + hop*HOPP + t] = z;
        }
    }
}

// ---------------------------------------------------------------------------
// Kernel 3: g_Wbf[n][k] (K-major B), blocks [Wh | Wh | Wl]
// ---------------------------------------------------------------------------
__global__ __launch_bounds__(512) void build_wbf_kernel(const float* __restrict__ W) {
    const int n = blockIdx.x;   // 0..511
    for (int k = threadIdx.x; k < KTOT; k += 512) {
        int blk = k / KBLK;
        int kk  = k - blk*KBLK;
        int hop = kk >> 9;
        int tp  = kk & 511;
        float v = 0.f;
        if (tp < TB && n < TB) v = W[((size_t)hop*TB + tp)*TB + n];
        __nv_bfloat16 hv = __float2bfloat16(v);
        __nv_bfloat16 ov = hv;
        if (blk == 2) ov = __float2bfloat16(v - __bfloat162float(hv));
        g_Wbf[(size_t)n*KTOT + k] = ov;
    }
}

// ---------------------------------------------------------------------------
// Kernel 4: mma.sync bf16 GEMM: g_C = Xbf * Wbf^T (both K-major)
//   block 128x128x32, 256 thr (8 warps, warp tile 64x32), 3-stage cp.async,
//   grid 176, 2 CTAs/SM hint. A K-chunks >=96 remapped to block 0 (Xh reuse).
// ---------------------------------------------------------------------------

// Swizzle for 64B rows packed as 128B atoms of 2 rows; conflict-free for
// ldmatrix 8-row groups and cp.async 16B stores (verified in R6).
__device__ __forceinline__ uint32_t sw_off(int r, int c) {
    int chunk8 = ((r & 1) << 2) | c;
    return (uint32_t)((r >> 1) * 128 + ((chunk8 ^ ((r >> 1) & 7)) << 4));
}

__device__ __forceinline__ uint32_t smem_u32(const void* p) {
    uint32_t a;
    asm("{ .reg .u64 t; cvta.to.shared.u64 t, %1; cvt.u32.u64 %0, t; }" : "=r"(a) : "l"(p));
    return a;
}
__device__ __forceinline__ void cp16(uint32_t dst, const void* src) {
    asm volatile("cp.async.cg.shared.global [%0], [%1], 16;" :: "r"(dst), "l"(src));
}
__device__ __forceinline__ void ldm_x4(uint32_t* q, uint32_t addr) {
    asm volatile("ldmatrix.sync.aligned.m8n8.x4.shared.b16 {%0,%1,%2,%3}, [%4];"
                 : "=r"(q[0]), "=r"(q[1]), "=r"(q[2]), "=r"(q[3]) : "r"(addr));
}
__device__ __forceinline__ void mma_bf16(float* c, const uint32_t* a, uint32_t b0, uint32_t b1) {
    asm volatile("mma.sync.aligned.m16n8k16.row.col.f32.bf16.bf16.f32 "
                 "{%0,%1,%2,%3}, {%4,%5,%6,%7}, {%8,%9}, {%0,%1,%2,%3};"
                 : "+f"(c[0]), "+f"(c[1]), "+f"(c[2]), "+f"(c[3])
                 : "r"(a[0]), "r"(a[1]), "r"(a[2]), "r"(a[3]), "r"(b0), "r"(b1));
}

#define A_ST 8192   // 128 rows * 64B
#define B_ST 8192

__global__ void __launch_bounds__(THREADS, 2) gemm_mma_kernel() {
    __shared__ __align__(128) unsigned char smem[STAGES*(A_ST + B_ST)];  // 48 KB

    const int tid  = threadIdx.x;
    const int lane = tid & 31;
    const int wid  = tid >> 5;
    const int wm   = wid & 1;        // 2 warps over M (64 rows each)
    const int wn   = wid >> 1;       // 4 warps over N (32 cols each)
    const int row0 = blockIdx.y * BM;
    const int n0   = blockIdx.x * BN;

    const uint32_t sA0 = smem_u32(smem);
    const uint32_t sB0 = sA0 + STAGES*A_ST;

    const char* gA = reinterpret_cast<const char*>(g_Xbf);
    const char* gB = reinterpret_cast<const char*>(g_Wbf);

    // per-thread load mapping: A chunks {tid, tid+256}, B chunks {tid, tid+256}
    const int a_r0 = tid >> 2, a_c = tid & 3;          // chunk 0: rows 0..63
    const uint32_t aoff0 = sw_off(a_r0,      a_c);
    const uint32_t aoff1 = sw_off(a_r0 + 64, a_c);
    const uint32_t boff0 = sw_off(a_r0,      a_c);
    const uint32_t boff1 = sw_off(a_r0 + 64, a_c);
    const char* aptr0 = gA + ((size_t)(row0 + a_r0     ) * KTOTA + a_c*8) * 2;
    const char* aptr1 = gA + ((size_t)(row0 + a_r0 + 64) * KTOTA + a_c*8) * 2;
    const char* bptr0 = gB + ((size_t)(n0   + a_r0     ) * KTOT  + a_c*8) * 2;
    const char* bptr1 = gB + ((size_t)(n0   + a_r0 + 64) * KTOT  + a_c*8) * 2;

    float acc[4][4][4];
    #pragma unroll
    for (int i = 0; i < 4; i++)
        #pragma unroll
        for (int j = 0; j < 4; j++)
            #pragma unroll
            for (int q = 0; q < 4; q++) acc[i][j][q] = 0.f;

    // prologue: stages 0 and 1 (chunks 0, 1)
    #pragma unroll
    for (int s = 0; s < 2; s++) {
        const size_t ab = (size_t)s * BK * 2;  // chunks 0,1 are < 96: no remap
        cp16(sA0 + s*A_ST + aoff0, aptr0 + ab);
        cp16(sA0 + s*A_ST + aoff1, aptr1 + ab);
        cp16(sB0 + s*B_ST + boff0, bptr0 + ab);
        cp16(sB0 + s*B_ST + boff1, bptr1 + ab);
        asm volatile("cp.async.commit_group;" ::: "memory");
    }

    const int lr = lane & 15;          // row within 16-row group
    const int lc = lane >> 4;          // k chunk half

    int stc = 0;   // stage of kb
    int stl = 2;   // stage to load (kb+2)
    for (int kb = 0; kb < KT; kb++) {
        asm volatile("cp.async.wait_group 1;" ::: "memory");
        __syncthreads();

        // issue loads for chunk kb+2 into stage stl (buffer of kb-1: free)
        const int ns = kb + 2;
        if (ns < KT) {
            const int ans = (ns >= 96) ? ns - 96 : ns;   // A block-2 -> block-0
            const size_t ab = (size_t)ans * BK * 2;
            const size_t bb = (size_t)ns  * BK * 2;
            const uint32_t sa_l = sA0 + stl*A_ST;
            const uint32_t sb_l = sB0 + stl*B_ST;
            cp16(sa_l + aoff0, aptr0 + ab);
            cp16(sa_l + aoff1, aptr1 + ab);
            cp16(sb_l + boff0, bptr0 + bb);
            cp16(sb_l + boff1, bptr1 + bb);
        }
        asm volatile("cp.async.commit_group;" ::: "memory");

        // compute stage stc (32 K = two 16-K sub-chunks)
        const uint32_t sa = sA0 + stc*A_ST;
        const uint32_t sb = sB0 + stc*B_ST;

        #pragma unroll
        for (int ks = 0; ks < 2; ks++) {
            const int c = ks*2 + lc;
            uint32_t af[4][4];
            #pragma unroll
            for (int mi = 0; mi < 4; mi++)
                ldm_x4(af[mi], sa + sw_off(wm*64 + mi*16 + lr, c));
            uint32_t bq0[4], bq1[4];
            ldm_x4(bq0, sb + sw_off(wn*32 +  0 + lr, c));
            ldm_x4(bq1, sb + sw_off(wn*32 + 16 + lr, c));
            #pragma unroll
            for (int mi = 0; mi < 4; mi++) {
                mma_bf16(acc[mi][0], af[mi], bq0[0], bq0[2]);
                mma_bf16(acc[mi][1], af[mi], bq0[1], bq0[3]);
                mma_bf16(acc[mi][2], af[mi], bq1[0], bq1[2]);
                mma_bf16(acc[mi][3], af[mi], bq1[1], bq1[3]);
            }
        }

        stc = (stc == STAGES-1) ? 0 : stc + 1;
        stl = (stl == STAGES-1) ? 0 : stl + 1;
    }

    // ---- epilogue: fragments -> g_C ----
    const int crow = lane >> 2;
    const int ccol = (lane & 3) * 2;
    #pragma unroll
    for (int mi = 0; mi < 4; mi++) {
        const int r = row0 + wm*64 + mi*16 + crow;
        #pragma unroll
        for (int ni = 0; ni < 4; ni++) {
            const int cbase = n0 + wn*32 + ni*8 + ccol;
            *reinterpret_cast<float2*>(&g_C[(size_t)r      *NTOT + cbase]) =
                make_float2(acc[mi][ni][0], acc[mi][ni][1]);
            *reinterpret_cast<float2*>(&g_C[(size_t)(r + 8)*NTOT + cbase]) =
                make_float2(acc[mi][ni][2], acc[mi][ni][3]);
        }
    }
}

// ---------------------------------------------------------------------------
// Kernel 5: out[b, e, n, :] = g_C[b*22+n, 0:500] + bias, for all e
// ---------------------------------------------------------------------------
__global__ __launch_bounds__(256) void replicate_kernel(
    const float* __restrict__ bias, float* __restrict__ out, int E)
{
    const int half = threadIdx.x >> 7;            // 0 or 1
    const int t4   = threadIdx.x & 127;           // float4 index in row
    const int m = blockIdx.x * 2 + half;          // 0..5631
    if (t4 >= TB/4) return;
    const int bb = m / NNODES, nn = m - bb*NNODES;
    float4 v  = *reinterpret_cast<const float4*>(&g_C[(size_t)m*NTOT + t4*4]);
    float4 bv = *reinterpret_cast<const float4*>(&bias[t4*4]);
    v.x += bv.x; v.y += bv.y; v.z += bv.z; v.w += bv.w;
    float* p = out + (size_t)bb * E * (NNODES*TB) + (size_t)nn * TB + t4*4;
    #pragma unroll 4
    for (int e = 0; e < E; e++) {
        *reinterpret_cast<float4*>(p) = v;
        p += NNODES*TB;
    }
}

// ---------------------------------------------------------------------------
// Launch. Inputs: x, adj, W, b, emb_size.
// ---------------------------------------------------------------------------
extern "C" void kernel_launch(void* const* d_in, const int* in_sizes, int n_in,
                              void* d_out, int out_size) {
    const float* x    = (const float*)d_in[0];
    const float* adj  = (const float*)d_in[1];
    const float* Wmat = (const float*)d_in[2];
    const float* bias = (const float*)d_in[3];
    float* out = (float*)d_out;
    const int E = out_size / (BATCH * NNODES * TB);

    prep_adj_kernel<<<1, 512>>>(adj);
    build_xbf_kernel<<<BATCH, 512>>>(x);
    build_wbf_kernel<<<NTOT, 512>>>(Wmat);

    dim3 grid(NTOT / BN, MROWS / BM);   // (4, 44) = 176 blocks
    gemm_mma_kernel<<<grid, THREADS>>>();

    replicate_kernel<<<MROWS/2, 256>>>(bias, out, E);
}

// round 10
// speedup vs baseline: 1.2528x; 1.2039x over previous
#include <cuda_runtime.h>
#include <cuda_bf16.h>
#include <cstdint>

#define NNODES 22
#define TB     500
#define BATCH  256
#define MROWS  (BATCH*NNODES)   // 5632
#define HOPP   512              // padded per-hop K stride
#define KBLK   1536             // per split-block K (3 hops x 512)
#define KTOT   4608             // B: [Wh | Wh | Wl]
#define KTOTA  3072             // A: [Xh | Xl]  (block 2 re-reads block 0)
#define NTOT   512              // padded N

#define BM 64
#define BN 128
#define BK 64
#define KT 72                   // K-chunks of 64 (over B's 4608)
#define THREADS 128

typedef unsigned long long u64;

// ---------------- device scratch ------------------------------------------
__device__ float         g_A [NNODES*NNODES];
__device__ float         g_A2[NNODES*NNODES];
__device__ __nv_bfloat16 g_Xbf[(size_t)MROWS*KTOTA];  // 34.6 MB
__device__ __nv_bfloat16 g_Wbf[(size_t)NTOT*KTOT];    // 4.7 MB
__device__ float         g_C  [(size_t)MROWS*NTOT];   // 11.5 MB

// ---------------------------------------------------------------------------
// Kernel 1: A = softmax(adj), A2 = A@A
// ---------------------------------------------------------------------------
__global__ void prep_adj_kernel(const float* __restrict__ adj) {
    __shared__ float sA[NNODES*NNODES];
    int tid = threadIdx.x;
    if (tid < NNODES) {
        float e[NNODES], mx = -1e30f;
        #pragma unroll
        for (int j = 0; j < NNODES; j++) mx = fmaxf(mx, adj[tid*NNODES + j]);
        float s = 0.f;
        #pragma unroll
        for (int j = 0; j < NNODES; j++) { e[j] = expf(adj[tid*NNODES + j] - mx); s += e[j]; }
        float inv = 1.f / s;
        #pragma unroll
        for (int j = 0; j < NNODES; j++) {
            float v = e[j] * inv;
            sA[tid*NNODES + j] = v;
            g_A[tid*NNODES + j] = v;
        }
    }
    __syncthreads();
    if (tid < NNODES*NNODES) {
        int n = tid / NNODES, m = tid - n*NNODES;
        float s = 0.f;
        #pragma unroll
        for (int k = 0; k < NNODES; k++) s = fmaf(sA[n*NNODES + k], sA[k*NNODES + m], s);
        g_A2[tid] = s;
    }
}

// ---------------------------------------------------------------------------
// Kernel 2: g_Xbf = bf16 split of [x | Ax | A2x], K-blocks [hi | lo]
// ---------------------------------------------------------------------------
__global__ __launch_bounds__(512) void build_xbf_kernel(const float* __restrict__ x) {
    __shared__ float sA[NNODES*NNODES], sA2[NNODES*NNODES];
    const int b = blockIdx.x;
    for (int i = threadIdx.x; i < NNODES*NNODES; i += blockDim.x) {
        sA[i] = g_A[i]; sA2[i] = g_A2[i];
    }
    __syncthreads();

    const int t = threadIdx.x;
    __nv_bfloat16* Xb = g_Xbf + (size_t)b * NNODES * KTOTA;

    if (t < TB) {
        float xv[NNODES];
        const float* xb = x + (size_t)b * NNODES * TB;
        #pragma unroll
        for (int m = 0; m < NNODES; m++) xv[m] = xb[m*TB + t];
        #pragma unroll
        for (int n = 0; n < NNODES; n++) {
            float h1 = 0.f, h2 = 0.f;
            #pragma unroll
            for (int m = 0; m < NNODES; m++) {
                h1 = fmaf(sA [n*NNODES + m], xv[m], h1);
                h2 = fmaf(sA2[n*NNODES + m], xv[m], h2);
            }
            float v0 = xv[n];
            __nv_bfloat16 hi0 = __float2bfloat16(v0);
            __nv_bfloat16 hi1 = __float2bfloat16(h1);
            __nv_bfloat16 hi2 = __float2bfloat16(h2);
            __nv_bfloat16 lo0 = __float2bfloat16(v0 - __bfloat162float(hi0));
            __nv_bfloat16 lo1 = __float2bfloat16(h1 - __bfloat162float(hi1));
            __nv_bfloat16 lo2 = __float2bfloat16(h2 - __bfloat162float(hi2));
            __nv_bfloat16* R = Xb + (size_t)n * KTOTA;
            R[t] = hi0;  R[HOPP + t] = hi1;  R[2*HOPP + t] = hi2;
            R[KBLK + t] = lo0;  R[KBLK + HOPP + t] = lo1;  R[KBLK + 2*HOPP + t] = lo2;
        }
    } else {  // t in [500, 512): zero padding columns
        __nv_bfloat16 z = __float2bfloat16(0.f);
        #pragma unroll
        for (int n = 0; n < NNODES; n++) {
            __nv_bfloat16* R = Xb + (size_t)n * KTOTA;
            #pragma unroll
            for (int blk = 0; blk < 2; blk++)
                #pragma unroll
                for (int hop = 0; hop < 3; hop++)
                    R[blk*KBLK + hop*HOPP + t] = z;
        }
    }
}

// ---------------------------------------------------------------------------
// Kernel 3: g_Wbf[n][k] (K-major B), blocks [Wh | Wh | Wl]
// ---------------------------------------------------------------------------
__global__ __launch_bounds__(512) void build_wbf_kernel(const float* __restrict__ W) {
    const int n = blockIdx.x;   // 0..511
    for (int k = threadIdx.x; k < KTOT; k += 512) {
        int blk = k / KBLK;
        int kk  = k - blk*KBLK;
        int hop = kk >> 9;
        int tp  = kk & 511;
        float v = 0.f;
        if (tp < TB && n < TB) v = W[((size_t)hop*TB + tp)*TB + n];
        __nv_bfloat16 hv = __float2bfloat16(v);
        __nv_bfloat16 ov = hv;
        if (blk == 2) ov = __float2bfloat16(v - __bfloat162float(hv));
        g_Wbf[(size_t)n*KTOT + k] = ov;
    }
}

// ---------------------------------------------------------------------------
// Kernel 4: mma.sync bf16 GEMM: g_C = Xbf * Wbf^T (both K-major)
//   block 64x128x64, 128 thr (4 warps over N, warp tile 64x32),
//   2-stage cp.async (wait 0 -> sync -> load next -> compute),
//   register fragment double-buffer. grid (4,88)=352, 3 CTAs/SM.
// ---------------------------------------------------------------------------

// SW128 swizzle: 128B rows, c = 16B chunk (0..7). Conflict-free for
// ldmatrix 8-row groups and cp.async stores.
__device__ __forceinline__ uint32_t sw128(int r, int c) {
    return (uint32_t)(r*128 + ((c ^ (r & 7)) << 4));
}

__device__ __forceinline__ uint32_t smem_u32(const void* p) {
    uint32_t a;
    asm("{ .reg .u64 t; cvta.to.shared.u64 t, %1; cvt.u32.u64 %0, t; }" : "=r"(a) : "l"(p));
    return a;
}
__device__ __forceinline__ void cp16(uint32_t dst, const void* src) {
    asm volatile("cp.async.cg.shared.global [%0], [%1], 16;" :: "r"(dst), "l"(src));
}
__device__ __forceinline__ void ldm_x4(uint32_t* q, uint32_t addr) {
    asm volatile("ldmatrix.sync.aligned.m8n8.x4.shared.b16 {%0,%1,%2,%3}, [%4];"
                 : "=r"(q[0]), "=r"(q[1]), "=r"(q[2]), "=r"(q[3]) : "r"(addr));
}
__device__ __forceinline__ void mma_bf16(float* c, const uint32_t* a, uint32_t b0, uint32_t b1) {
    asm volatile("mma.sync.aligned.m16n8k16.row.col.f32.bf16.bf16.f32 "
                 "{%0,%1,%2,%3}, {%4,%5,%6,%7}, {%8,%9}, {%0,%1,%2,%3};"
                 : "+f"(c[0]), "+f"(c[1]), "+f"(c[2]), "+f"(c[3])
                 : "r"(a[0]), "r"(a[1]), "r"(a[2]), "r"(a[3]), "r"(b0), "r"(b1));
}

#define A_ST 8192    // 64 rows * 128B
#define B_ST 16384   // 128 rows * 128B

__global__ void __launch_bounds__(THREADS, 3) gemm_mma_kernel() {
    __shared__ __align__(128) unsigned char smem[2*(A_ST + B_ST)];  // 48 KB

    const int tid  = threadIdx.x;
    const int lane = tid & 31;
    const int wn   = tid >> 5;       // 4 warps over N (32 cols each)
    const int row0 = blockIdx.y * BM;
    const int n0   = blockIdx.x * BN;

    const uint32_t sA0 = smem_u32(smem);
    const uint32_t sB0 = sA0 + 2*A_ST;

    const char* gA = reinterpret_cast<const char*>(g_Xbf);
    const char* gB = reinterpret_cast<const char*>(g_Wbf);

    // loader mapping: thread t handles (r = i*16 + t>>3, c = t&7)
    const int l_r = tid >> 3, l_c = tid & 7;
    const uint32_t aoff0 = sw128(l_r, l_c);   // +i*2048 for i-th 16-row group
    const char* aptrb = gA + ((size_t)(row0 + l_r) * KTOTA + l_c*8) * 2;
    const char* bptrb = gB + ((size_t)(n0   + l_r) * KTOT  + l_c*8) * 2;
    const size_t A_RSTEP = (size_t)16 * KTOTA * 2;  // 16 rows of A
    const size_t B_RSTEP = (size_t)16 * KTOT  * 2;  // 16 rows of B

    float acc[4][4][4];
    #pragma unroll
    for (int i = 0; i < 4; i++)
        #pragma unroll
        for (int j = 0; j < 4; j++)
            #pragma unroll
            for (int q = 0; q < 4; q++) acc[i][j][q] = 0.f;

    // prologue: chunk 0 -> stage 0
    #pragma unroll
    for (int i = 0; i < 4; i++) cp16(sA0 + aoff0 + i*2048, aptrb + i*A_RSTEP);
    #pragma unroll
    for (int i = 0; i < 8; i++) cp16(sB0 + aoff0 + i*2048, bptrb + i*B_RSTEP);
    asm volatile("cp.async.commit_group;" ::: "memory");

    const int lr = lane & 15;          // row within 16-row group
    const int lc = lane >> 4;          // 16B half of the 32B k-sub-chunk

    uint32_t afr[2][4][4];             // [buf][mi][frag]
    uint32_t bfr[2][2][4];             // [buf][n-half][frag]

    for (int kb = 0; kb < KT; kb++) {
        // chunk kb fully arrived (own groups), then barrier for cross-thread
        // visibility AND to guarantee all warps finished compute kb-1 before
        // stage (kb+1)&1 (which held kb-1) is overwritten below.
        asm volatile("cp.async.wait_group 0;" ::: "memory");
        __syncthreads();

        // load chunk kb+1 into stage (kb+1)&1 (overlaps compute kb below)
        const int ns = kb + 1;
        if (ns < KT) {
            const int ans = (ns >= 48) ? ns - 48 : ns;   // A block-2 -> block-0
            const size_t ab = (size_t)ans * BK * 2;
            const size_t bb = (size_t)ns  * BK * 2;
            const uint32_t sa_l = sA0 + (ns & 1)*A_ST;
            const uint32_t sb_l = sB0 + (ns & 1)*B_ST;
            #pragma unroll
            for (int i = 0; i < 4; i++) cp16(sa_l + aoff0 + i*2048, aptrb + i*A_RSTEP + ab);
            #pragma unroll
            for (int i = 0; i < 8; i++) cp16(sb_l + aoff0 + i*2048, bptrb + i*B_RSTEP + bb);
            asm volatile("cp.async.commit_group;" ::: "memory");
        }

        const uint32_t sa = sA0 + (kb & 1)*A_ST;
        const uint32_t sb = sB0 + (kb & 1)*B_ST;

        // preload ks=0 fragments
        {
            const int c = lc;
            #pragma unroll
            for (int mi = 0; mi < 4; mi++)
                ldm_x4(afr[0][mi], sa + sw128(mi*16 + lr, c));
            ldm_x4(bfr[0][0], sb + sw128(wn*32 +  0 + lr, c));
            ldm_x4(bfr[0][1], sb + sw128(wn*32 + 16 + lr, c));
        }
        #pragma unroll
        for (int ks = 0; ks < 4; ks++) {
            const int cur = ks & 1, nxt = cur ^ 1;
            if (ks < 3) {
                const int c = (ks+1)*2 + lc;
                #pragma unroll
                for (int mi = 0; mi < 4; mi++)
                    ldm_x4(afr[nxt][mi], sa + sw128(mi*16 + lr, c));
                ldm_x4(bfr[nxt][0], sb + sw128(wn*32 +  0 + lr, c));
                ldm_x4(bfr[nxt][1], sb + sw128(wn*32 + 16 + lr, c));
            }
            #pragma unroll
            for (int mi = 0; mi < 4; mi++) {
                mma_bf16(acc[mi][0], afr[cur][mi], bfr[cur][0][0], bfr[cur][0][2]);
                mma_bf16(acc[mi][1], afr[cur][mi], bfr[cur][0][1], bfr[cur][0][3]);
                mma_bf16(acc[mi][2], afr[cur][mi], bfr[cur][1][0], bfr[cur][1][2]);
                mma_bf16(acc[mi][3], afr[cur][mi], bfr[cur][1][1], bfr[cur][1][3]);
            }
        }
    }

    // ---- epilogue: fragments -> g_C ----
    const int crow = lane >> 2;
    const int ccol = (lane & 3) * 2;
    #pragma unroll
    for (int mi = 0; mi < 4; mi++) {
        const int r = row0 + mi*16 + crow;
        #pragma unroll
        for (int ni = 0; ni < 4; ni++) {
            const int cbase = n0 + wn*32 + ni*8 + ccol;
            *reinterpret_cast<float2*>(&g_C[(size_t)r      *NTOT + cbase]) =
                make_float2(acc[mi][ni][0], acc[mi][ni][1]);
            *reinterpret_cast<float2*>(&g_C[(size_t)(r + 8)*NTOT + cbase]) =
                make_float2(acc[mi][ni][2], acc[mi][ni][3]);
        }
    }
}

// ---------------------------------------------------------------------------
// Kernel 5: out[b, e, n, :] = g_C[b*22+n, 0:500] + bias, for all e
// ---------------------------------------------------------------------------
__global__ __launch_bounds__(256) void replicate_kernel(
    const float* __restrict__ bias, float* __restrict__ out, int E)
{
    const int half = threadIdx.x >> 7;            // 0 or 1
    const int t4   = threadIdx.x & 127;           // float4 index in row
    const int m = blockIdx.x * 2 + half;          // 0..5631
    if (t4 >= TB/4) return;
    const int bb = m / NNODES, nn = m - bb*NNODES;
    float4 v  = *reinterpret_cast<const float4*>(&g_C[(size_t)m*NTOT + t4*4]);
    float4 bv = *reinterpret_cast<const float4*>(&bias[t4*4]);
    v.x += bv.x; v.y += bv.y; v.z += bv.z; v.w += bv.w;
    float* p = out + (size_t)bb * E * (NNODES*TB) + (size_t)nn * TB + t4*4;
    #pragma unroll 4
    for (int e = 0; e < E; e++) {
        *reinterpret_cast<float4*>(p) = v;
        p += NNODES*TB;
    }
}

// ---------------------------------------------------------------------------
// Launch. Inputs: x, adj, W, b, emb_size.
// ---------------------------------------------------------------------------
extern "C" void kernel_launch(void* const* d_in, const int* in_sizes, int n_in,
                              void* d_out, int out_size) {
    const float* x    = (const float*)d_in[0];
    const float* adj  = (const float*)d_in[1];
    const float* Wmat = (const float*)d_in[2];
    const float* bias = (const float*)d_in[3];
    float* out = (float*)d_out;
    const int E = out_size / (BATCH * NNODES * TB);

    prep_adj_kernel<<<1, 512>>>(adj);
    build_xbf_kernel<<<BATCH, 512>>>(x);
    build_wbf_kernel<<<NTOT, 512>>>(Wmat);

    dim3 grid(NTOT / BN, MROWS / BM);   // (4, 88) = 352 blocks
    gemm_mma_kernel<<<grid, THREADS>>>();

    replicate_kernel<<<MROWS/2, 256>>>(bias, out, E);
}

// round 13
// speedup vs baseline: 1.4244x; 1.1369x over previous
#include <cuda_runtime.h>
#include <cuda_bf16.h>
#include <cstdint>

#define NNODES 22
#define TB     500
#define BATCH  256
#define MROWS  (BATCH*NNODES)   // 5632
#define HOPP   512              // padded per-hop K stride
#define KBLK   1536             // per split-block K (3 hops x 512)
#define KTOT   4608             // B: [Wh | Wh | Wl]
#define KTOTA  3072             // A: [Xh | Xl]  (block 2 re-reads block 0)
#define NTOT   512              // padded N

#define BM 64
#define BN 128
#define BK 64
#define KT 72                   // K-chunks of 64 (over B's 4608)
#define KHALF 36                // chunks per split-K CTA
#define THREADS 128

typedef unsigned long long u64;

// ---------------- device scratch ------------------------------------------
__device__ __nv_bfloat16 g_Xbf[(size_t)MROWS*KTOTA];  // 34.6 MB
__device__ __nv_bfloat16 g_Wbf[(size_t)NTOT*KTOT];    // 4.7 MB
__device__ float         g_C0 [(size_t)MROWS*NTOT];   // 11.5 MB
__device__ float         g_C1 [(size_t)MROWS*NTOT];   // 11.5 MB

// ---------------------------------------------------------------------------
// Kernel 1: g_Xbf = bf16 split of [x | Ax | A2x], K-blocks [hi | lo]
//   A = softmax(adj) and A2 = A@A computed per-block in smem (cheap).
// ---------------------------------------------------------------------------
__global__ __launch_bounds__(512) void build_xbf_kernel(
    const float* __restrict__ x, const float* __restrict__ adj)
{
    __shared__ float sA[NNODES*NNODES], sA2[NNODES*NNODES];
    const int tid = threadIdx.x;

    if (tid < NNODES) {
        float e[NNODES], mx = -1e30f;
        #pragma unroll
        for (int j = 0; j < NNODES; j++) mx = fmaxf(mx, adj[tid*NNODES + j]);
        float s = 0.f;
        #pragma unroll
        for (int j = 0; j < NNODES; j++) { e[j] = expf(adj[tid*NNODES + j] - mx); s += e[j]; }
        float inv = 1.f / s;
        #pragma unroll
        for (int j = 0; j < NNODES; j++) sA[tid*NNODES + j] = e[j] * inv;
    }
    __syncthreads();
    if (tid < NNODES*NNODES) {
        int n = tid / NNODES, m = tid - n*NNODES;
        float s = 0.f;
        #pragma unroll
        for (int k = 0; k < NNODES; k++) s = fmaf(sA[n*NNODES + k], sA[k*NNODES + m], s);
        sA2[tid] = s;
    }
    __syncthreads();

    const int b = blockIdx.x;
    const int t = tid;
    __nv_bfloat16* Xb = g_Xbf + (size_t)b * NNODES * KTOTA;

    if (t < TB) {
        float xv[NNODES];
        const float* xb = x + (size_t)b * NNODES * TB;
        #pragma unroll
        for (int m = 0; m < NNODES; m++) xv[m] = xb[m*TB + t];
        #pragma unroll
        for (int n = 0; n < NNODES; n++) {
            float h1 = 0.f, h2 = 0.f;
            #pragma unroll
            for (int m = 0; m < NNODES; m++) {
                h1 = fmaf(sA [n*NNODES + m], xv[m], h1);
                h2 = fmaf(sA2[n*NNODES + m], xv[m], h2);
            }
            float v0 = xv[n];
            __nv_bfloat16 hi0 = __float2bfloat16(v0);
            __nv_bfloat16 hi1 = __float2bfloat16(h1);
            __nv_bfloat16 hi2 = __float2bfloat16(h2);
            __nv_bfloat16 lo0 = __float2bfloat16(v0 - __bfloat162float(hi0));
            __nv_bfloat16 lo1 = __float2bfloat16(h1 - __bfloat162float(hi1));
            __nv_bfloat16 lo2 = __float2bfloat16(h2 - __bfloat162float(hi2));
            __nv_bfloat16* R = Xb + (size_t)n * KTOTA;
            R[t] = hi0;  R[HOPP + t] = hi1;  R[2*HOPP + t] = hi2;
            R[KBLK + t] = lo0;  R[KBLK + HOPP + t] = lo1;  R[KBLK + 2*HOPP + t] = lo2;
        }
    } else if (t < HOPP) {  // t in [500, 512): zero padding columns
        __nv_bfloat16 z = __float2bfloat16(0.f);
        #pragma unroll
        for (int n = 0; n < NNODES; n++) {
            __nv_bfloat16* R = Xb + (size_t)n * KTOTA;
            #pragma unroll
            for (int blk = 0; blk < 2; blk++)
                #pragma unroll
                for (int hop = 0; hop < 3; hop++)
                    R[blk*KBLK + hop*HOPP + t] = z;
        }
    }
}

// ---------------------------------------------------------------------------
// Kernel 2: g_Wbf[n][k] (K-major B), blocks [Wh | Wh | Wl].
//   32x32 smem-transpose tiles, 256-thread blocks (32x8, 4 rows per thread).
//   Coalesced reads of W rows, coalesced writes of g_Wbf rows.
//   grid (16 n-tiles, 16 tp-tiles, 3 hops), block (32, 8).
// ---------------------------------------------------------------------------
__global__ __launch_bounds__(256) void build_wbf_kernel(const float* __restrict__ W) {
    __shared__ float sm[32][33];
    const int n0  = blockIdx.x * 32;
    const int tp0 = blockIdx.y * 32;
    const int hop = blockIdx.z;
    const int tx = threadIdx.x, ty0 = threadIdx.y;

    #pragma unroll
    for (int i = 0; i < 4; i++) {
        const int ty = ty0 + i*8;
        const int tp = tp0 + ty, n = n0 + tx;
        float v = 0.f;
        if (tp < TB && n < TB) v = W[((size_t)hop*TB + tp)*TB + n];
        sm[ty][tx] = v;
    }
    __syncthreads();

    #pragma unroll
    for (int i = 0; i < 4; i++) {
        const int ty = ty0 + i*8;
        // write: row n0+ty of g_Wbf, k = hop*HOPP + tp0 + tx (coalesced in tx)
        const float vt = sm[tx][ty];
        __nv_bfloat16 hv = __float2bfloat16(vt);
        __nv_bfloat16 lv = __float2bfloat16(vt - __bfloat162float(hv));
        __nv_bfloat16* R = g_Wbf + (size_t)(n0 + ty) * KTOT + hop*HOPP + tp0 + tx;
        R[0]      = hv;   // block 0: Wh
        R[KBLK]   = hv;   // block 1: Wh
        R[2*KBLK] = lv;   // block 2: Wl
    }
}

// ---------------------------------------------------------------------------
// Kernel 3: mma.sync bf16 GEMM, split-K x2:
//   CTA z computes K-chunks [z*36, z*36+36) -> g_Cz.
//   block 64x128x64, 128 thr, 2-stage cp.async, reg frag double-buffer.
//   grid (4, 88, 2) = 704 CTAs.
// ---------------------------------------------------------------------------
__device__ __forceinline__ uint32_t sw128(int r, int c) {
    return (uint32_t)(r*128 + ((c ^ (r & 7)) << 4));
}
__device__ __forceinline__ uint32_t smem_u32(const void* p) {
    uint32_t a;
    asm("{ .reg .u64 t; cvta.to.shared.u64 t, %1; cvt.u32.u64 %0, t; }" : "=r"(a) : "l"(p));
    return a;
}
__device__ __forceinline__ void cp16(uint32_t dst, const void* src) {
    asm volatile("cp.async.cg.shared.global [%0], [%1], 16;" :: "r"(dst), "l"(src));
}
__device__ __forceinline__ void ldm_x4(uint32_t* q, uint32_t addr) {
    asm volatile("ldmatrix.sync.aligned.m8n8.x4.shared.b16 {%0,%1,%2,%3}, [%4];"
                 : "=r"(q[0]), "=r"(q[1]), "=r"(q[2]), "=r"(q[3]) : "r"(addr));
}
__device__ __forceinline__ void mma_bf16(float* c, const uint32_t* a, uint32_t b0, uint32_t b1) {
    asm volatile("mma.sync.aligned.m16n8k16.row.col.f32.bf16.bf16.f32 "
                 "{%0,%1,%2,%3}, {%4,%5,%6,%7}, {%8,%9}, {%0,%1,%2,%3};"
                 : "+f"(c[0]), "+f"(c[1]), "+f"(c[2]), "+f"(c[3])
                 : "r"(a[0]), "r"(a[1]), "r"(a[2]), "r"(a[3]), "r"(b0), "r"(b1));
}

#define A_ST 8192    // 64 rows * 128B
#define B_ST 16384   // 128 rows * 128B

__global__ void __launch_bounds__(THREADS, 3) gemm_mma_kernel() {
    __shared__ __align__(128) unsigned char smem[2*(A_ST + B_ST)];  // 48 KB

    const int tid  = threadIdx.x;
    const int lane = tid & 31;
    const int wn   = tid >> 5;       // 4 warps over N (32 cols each)
    const int row0 = blockIdx.y * BM;
    const int n0   = blockIdx.x * BN;
    const int z    = blockIdx.z;
    const int kb0  = z * KHALF;

    const uint32_t sA0 = smem_u32(smem);
    const uint32_t sB0 = sA0 + 2*A_ST;

    const char* gA = reinterpret_cast<const char*>(g_Xbf);
    const char* gB = reinterpret_cast<const char*>(g_Wbf);

    // loader mapping: thread t handles (r = i*16 + t>>3, c = t&7)
    const int l_r = tid >> 3, l_c = tid & 7;
    const uint32_t aoff0 = sw128(l_r, l_c);   // +i*2048 for i-th 16-row group
    const char* aptrb = gA + ((size_t)(row0 + l_r) * KTOTA + l_c*8) * 2;
    const char* bptrb = gB + ((size_t)(n0   + l_r) * KTOT  + l_c*8) * 2;
    const size_t A_RSTEP = (size_t)16 * KTOTA * 2;
    const size_t B_RSTEP = (size_t)16 * KTOT  * 2;

    float acc[4][4][4];
    #pragma unroll
    for (int i = 0; i < 4; i++)
        #pragma unroll
        for (int j = 0; j < 4; j++)
            #pragma unroll
            for (int q = 0; q < 4; q++) acc[i][j][q] = 0.f;

    // prologue: chunk kb0 -> stage 0
    {
        const int ak = (kb0 >= 48) ? kb0 - 48 : kb0;
        const size_t ab = (size_t)ak  * BK * 2;
        const size_t bb = (size_t)kb0 * BK * 2;
        #pragma unroll
        for (int i = 0; i < 4; i++) cp16(sA0 + aoff0 + i*2048, aptrb + i*A_RSTEP + ab);
        #pragma unroll
        for (int i = 0; i < 8; i++) cp16(sB0 + aoff0 + i*2048, bptrb + i*B_RSTEP + bb);
        asm volatile("cp.async.commit_group;" ::: "memory");
    }

    const int lr = lane & 15;
    const int lc = lane >> 4;

    uint32_t afr[2][4][4];
    uint32_t bfr[2][2][4];

    for (int it = 0; it < KHALF; it++) {
        // own chunk-it group retired, then cross-thread visibility + compute
        // of it-1 finished before stage (it+1)&1 is overwritten below.
        asm volatile("cp.async.wait_group 0;" ::: "memory");
        __syncthreads();

        const int nit = it + 1;
        if (nit < KHALF) {
            const int ns = kb0 + nit;
            const int ans = (ns >= 48) ? ns - 48 : ns;
            const size_t ab = (size_t)ans * BK * 2;
            const size_t bb = (size_t)ns  * BK * 2;
            const uint32_t sa_l = sA0 + (nit & 1)*A_ST;
            const uint32_t sb_l = sB0 + (nit & 1)*B_ST;
            #pragma unroll
            for (int i = 0; i < 4; i++) cp16(sa_l + aoff0 + i*2048, aptrb + i*A_RSTEP + ab);
            #pragma unroll
            for (int i = 0; i < 8; i++) cp16(sb_l + aoff0 + i*2048, bptrb + i*B_RSTEP + bb);
            asm volatile("cp.async.commit_group;" ::: "memory");
        }

        const uint32_t sa = sA0 + (it & 1)*A_ST;
        const uint32_t sb = sB0 + (it & 1)*B_ST;

        {   // preload ks=0 fragments
            const int c = lc;
            #pragma unroll
            for (int mi = 0; mi < 4; mi++)
                ldm_x4(afr[0][mi], sa + sw128(mi*16 + lr, c));
            ldm_x4(bfr[0][0], sb + sw128(wn*32 +  0 + lr, c));
            ldm_x4(bfr[0][1], sb + sw128(wn*32 + 16 + lr, c));
        }
        #pragma unroll
        for (int ks = 0; ks < 4; ks++) {
            const int cur = ks & 1, nxt = cur ^ 1;
            if (ks < 3) {
                const int c = (ks+1)*2 + lc;
                #pragma unroll
                for (int mi = 0; mi < 4; mi++)
                    ldm_x4(afr[nxt][mi], sa + sw128(mi*16 + lr, c));
                ldm_x4(bfr[nxt][0], sb + sw128(wn*32 +  0 + lr, c));
                ldm_x4(bfr[nxt][1], sb + sw128(wn*32 + 16 + lr, c));
            }
            #pragma unroll
            for (int mi = 0; mi < 4; mi++) {
                mma_bf16(acc[mi][0], afr[cur][mi], bfr[cur][0][0], bfr[cur][0][2]);
                mma_bf16(acc[mi][1], afr[cur][mi], bfr[cur][0][1], bfr[cur][0][3]);
                mma_bf16(acc[mi][2], afr[cur][mi], bfr[cur][1][0], bfr[cur][1][2]);
                mma_bf16(acc[mi][3], afr[cur][mi], bfr[cur][1][1], bfr[cur][1][3]);
            }
        }
    }

    // ---- epilogue: fragments -> g_C{z} ----
    float* gC = (z == 0) ? g_C0 : g_C1;
    const int crow = lane >> 2;
    const int ccol = (lane & 3) * 2;
    #pragma unroll
    for (int mi = 0; mi < 4; mi++) {
        const int r = row0 + mi*16 + crow;
        #pragma unroll
        for (int ni = 0; ni < 4; ni++) {
            const int cbase = n0 + wn*32 + ni*8 + ccol;
            *reinterpret_cast<float2*>(&gC[(size_t)r      *NTOT + cbase]) =
                make_float2(acc[mi][ni][0], acc[mi][ni][1]);
            *reinterpret_cast<float2*>(&gC[(size_t)(r + 8)*NTOT + cbase]) =
                make_float2(acc[mi][ni][2], acc[mi][ni][3]);
        }
    }
}

// ---------------------------------------------------------------------------
// Kernel 4: out[b, e, n, :] = g_C0[m] + g_C1[m] + bias, replicated E times
// ---------------------------------------------------------------------------
__global__ __launch_bounds__(256) void replicate_kernel(
    const float* __restrict__ bias, float* __restrict__ out, int E)
{
    const int half = threadIdx.x >> 7;
    const int t4   = threadIdx.x & 127;
    const int m = blockIdx.x * 2 + half;
    if (t4 >= TB/4) return;
    const int bb = m / NNODES, nn = m - bb*NNODES;
    float4 v0 = *reinterpret_cast<const float4*>(&g_C0[(size_t)m*NTOT + t4*4]);
    float4 v1 = *reinterpret_cast<const float4*>(&g_C1[(size_t)m*NTOT + t4*4]);
    float4 bv = *reinterpret_cast<const float4*>(&bias[t4*4]);
    float4 v = make_float4(v0.x + v1.x + bv.x, v0.y + v1.y + bv.y,
                           v0.z + v1.z + bv.z, v0.w + v1.w + bv.w);
    float* p = out + (size_t)bb * E * (NNODES*TB) + (size_t)nn * TB + t4*4;
    #pragma unroll 4
    for (int e = 0; e < E; e++) {
        *reinterpret_cast<float4*>(p) = v;
        p += NNODES*TB;
    }
}

// ---------------------------------------------------------------------------
// Launch. Inputs: x, adj, W, b, emb_size.
// ---------------------------------------------------------------------------
extern "C" void kernel_launch(void* const* d_in, const int* in_sizes, int n_in,
                              void* d_out, int out_size) {
    const float* x    = (const float*)d_in[0];
    const float* adj  = (const float*)d_in[1];
    const float* Wmat = (const float*)d_in[2];
    const float* bias = (const float*)d_in[3];
    float* out = (float*)d_out;
    const int E = out_size / (BATCH * NNODES * TB);

    build_xbf_kernel<<<BATCH, 512>>>(x, adj);
    build_wbf_kernel<<<dim3(16, 16, 3), dim3(32, 8)>>>(Wmat);

    dim3 grid(NTOT / BN, MROWS / BM, 2);   // (4, 88, 2) = 704 CTAs
    gemm_mma_kernel<<<grid, THREADS>>>();

    replicate_kernel<<<MROWS/2, 256>>>(bias, out, E);
}